// round 1
// baseline (speedup 1.0000x reference)
#include <cuda_runtime.h>
#include <math.h>

// Problem constants
#define BB   8
#define CC   768
#define HH   56
#define LL   3136           // 56*56
#define NCAT 3840           // 5*768 (Q,K,V,Q1,K1 concatenated)
#define EPSF 1e-6f
#define BN_EPSF 1e-5f

// ---------------------------------------------------------------------------
// Scratch (device globals; no allocations allowed)
// ---------------------------------------------------------------------------
static __device__ __align__(16) float g_pe[LL * 64];
static __device__ __align__(16) float g_pos[LL * CC];
static __device__ __align__(16) float g_wcat[CC * NCAT];
static __device__ __align__(16) float g_bcat[NCAT];
static __device__ __align__(16) float g_t[(size_t)BB * LL * CC];
static __device__ __align__(16) float g_cat[(size_t)BB * LL * NCAT];
static __device__ __align__(16) float g_pkv[BB * 16 * CC];
static __device__ __align__(16) float g_pks[BB * 16 * CC];
static __device__ __align__(16) float g_kv[BB * CC];
static __device__ __align__(16) float g_ks[BB * CC];
static __device__ __align__(16) float g_res[(size_t)BB * LL * CC];
static __device__ __align__(16) float g_mid[(size_t)BB * CC * CC];
static __device__ __align__(16) float g_res2[(size_t)BB * LL * CC];

// ---------------------------------------------------------------------------
// Block-wide reductions (256 threads)
// ---------------------------------------------------------------------------
__device__ __forceinline__ float block_sum256(float v) {
    __shared__ float sm[8];
    int lane = threadIdx.x & 31, w = threadIdx.x >> 5;
#pragma unroll
    for (int o = 16; o; o >>= 1) v += __shfl_xor_sync(0xffffffffu, v, o);
    if (lane == 0) sm[w] = v;
    __syncthreads();
    float t = sm[lane & 7];
#pragma unroll
    for (int o = 4; o; o >>= 1) t += __shfl_xor_sync(0xffffffffu, t, o);
    return t;
}

__device__ __forceinline__ float block_max256(float v) {
    __shared__ float sm[8];
    int lane = threadIdx.x & 31, w = threadIdx.x >> 5;
#pragma unroll
    for (int o = 16; o; o >>= 1) v = fmaxf(v, __shfl_xor_sync(0xffffffffu, v, o));
    if (lane == 0) sm[w] = v;
    __syncthreads();
    float t = sm[lane & 7];
#pragma unroll
    for (int o = 4; o; o >>= 1) t = fmaxf(t, __shfl_xor_sync(0xffffffffu, t, o));
    return t;
}

// ---------------------------------------------------------------------------
// 1) Fourier features pe[L, 64]
// ---------------------------------------------------------------------------
__global__ void pe_kernel(void) {
    int idx = blockIdx.x * 256 + threadIdx.x;
    if (idx >= LL * 64) return;
    int l = idx >> 6, k = idx & 63;
    int kk = k & 31;
    float coord = (k < 32) ? (float)(l / HH + 1) : (float)(l % HH + 1);
    float v = coord / ((float)HH + EPSF) * 6.283185307179586f;   // 2*pi
    float dt = powf(10000.0f, (float)(kk & ~1) / 32.0f);
    float p = v / dt;
    g_pe[idx] = (kk & 1) ? cosf(p) : sinf(p);
}

// 2) pos[L, C] = pe @ pos_w + pos_b   (K = 64; tiny GEMM)
__global__ __launch_bounds__(256) void pos_kernel(const float* __restrict__ pw,
                                                  const float* __restrict__ pb) {
    __shared__ float pe_s[64];
    int l = blockIdx.x;
    int tid = threadIdx.x;
    if (tid < 64) pe_s[tid] = g_pe[l * 64 + tid];
    __syncthreads();
#pragma unroll
    for (int j = 0; j < 3; j++) {
        int c = tid + j * 256;
        float acc = pb[c];
#pragma unroll 16
        for (int k = 0; k < 64; k++) acc += pe_s[k] * pw[k * CC + c];
        g_pos[(size_t)l * CC + c] = acc;
    }
}

// 3) Concatenate the 5 projection weights/biases into [768, 3840] / [3840]
__global__ void wcat_kernel(const float* __restrict__ wq, const float* __restrict__ wk,
                            const float* __restrict__ wv, const float* __restrict__ wq1,
                            const float* __restrict__ wk1,
                            const float* __restrict__ bq, const float* __restrict__ bk,
                            const float* __restrict__ bv, const float* __restrict__ bq1,
                            const float* __restrict__ bk1) {
    int idx = blockIdx.x * 256 + threadIdx.x;
    if (idx < NCAT) {
        int g = idx / CC, c = idx % CC;
        const float* bp = (g == 0) ? bq : (g == 1) ? bk : (g == 2) ? bv : (g == 3) ? bq1 : bk1;
        g_bcat[idx] = bp[c];
    }
    if (idx >= CC * NCAT) return;
    int k = idx / NCAT, n = idx % NCAT;
    int g = n / CC, c = n % CC;
    const float* wp = (g == 0) ? wq : (g == 1) ? wk : (g == 2) ? wv : (g == 3) ? wq1 : wk1;
    g_wcat[idx] = wp[k * CC + c];
}

// 4) t[b, l, c] = x[b, c, l] + pos[l, c]   (tiled transpose)
__global__ __launch_bounds__(256) void addpos_kernel(const float* __restrict__ x) {
    __shared__ float tile[32][33];
    int tx = threadIdx.x & 31, ty = threadIdx.x >> 5;       // 32 x 8
    int l0 = blockIdx.x * 32, c0 = blockIdx.y * 32, b = blockIdx.z;
#pragma unroll
    for (int i = 0; i < 4; i++) {
        int c = c0 + ty + i * 8;
        tile[ty + i * 8][tx] = x[(size_t)(b * CC + c) * LL + l0 + tx];
    }
    __syncthreads();
#pragma unroll
    for (int i = 0; i < 4; i++) {
        int l = l0 + ty + i * 8;
        int c = c0 + tx;
        g_t[((size_t)b * LL + l) * CC + c] = tile[tx][ty + i * 8] + g_pos[(size_t)l * CC + c];
    }
}

// ---------------------------------------------------------------------------
// 5) Tiled SGEMM: C = op(A) @ B (+bias, conditional ReLU), batched via blockIdx.z
//    TRANSA=false: A is [M, K] (lda); TRANSA=true: A is [K, M] (lda) -> C = A^T B
//    BM=BN=128, BK=8, 256 threads, 8x8 per thread. N%128==0, K%8==0 required;
//    M handled with guards.
// ---------------------------------------------------------------------------
template <bool TRANSA>
__global__ __launch_bounds__(256) void sgemm(const float* __restrict__ A, int lda, size_t sA,
                                             const float* __restrict__ Bm, int ldb, size_t sB,
                                             float* __restrict__ Cm, int ldc, size_t sC,
                                             int M, int N, int K,
                                             const float* __restrict__ bias, int relu_limit) {
    __shared__ float As[8][128];
    __shared__ float Bs[8][128];
    A  += (size_t)blockIdx.z * sA;
    Bm += (size_t)blockIdx.z * sB;
    Cm += (size_t)blockIdx.z * sC;

    int tid = threadIdx.x;
    int tx = tid & 15, ty = tid >> 4;
    int m0 = blockIdx.y * 128, n0 = blockIdx.x * 128;

    int brow = tid >> 5, bcol = (tid & 31) << 2;   // B tile: 8 x 128, float4
    int arow, acol;
    if (TRANSA) { arow = brow; acol = bcol; }      // A tile like B tile
    else        { arow = tid >> 1; acol = (tid & 1) << 2; }

    float acc[8][8];
#pragma unroll
    for (int i = 0; i < 8; i++)
#pragma unroll
        for (int j = 0; j < 8; j++) acc[i][j] = 0.0f;

    for (int kb = 0; kb < K; kb += 8) {
        float4 av, bv;
        if (TRANSA) {
            av = *(const float4*)(A + (size_t)(kb + arow) * lda + m0 + acol);
        } else {
            av = make_float4(0.f, 0.f, 0.f, 0.f);
            if (m0 + arow < M)
                av = *(const float4*)(A + (size_t)(m0 + arow) * lda + kb + acol);
        }
        bv = *(const float4*)(Bm + (size_t)(kb + brow) * ldb + n0 + bcol);

        __syncthreads();
        if (TRANSA) {
            *(float4*)&As[arow][acol] = av;
        } else {
            As[acol + 0][arow] = av.x;
            As[acol + 1][arow] = av.y;
            As[acol + 2][arow] = av.z;
            As[acol + 3][arow] = av.w;
        }
        *(float4*)&Bs[brow][bcol] = bv;
        __syncthreads();

#pragma unroll
        for (int k = 0; k < 8; k++) {
            float a[8], bb[8];
            *(float4*)&a[0]  = *(float4*)&As[k][ty << 3];
            *(float4*)&a[4]  = *(float4*)&As[k][(ty << 3) + 4];
            *(float4*)&bb[0] = *(float4*)&Bs[k][tx << 3];
            *(float4*)&bb[4] = *(float4*)&Bs[k][(tx << 3) + 4];
#pragma unroll
            for (int i = 0; i < 8; i++)
#pragma unroll
                for (int j = 0; j < 8; j++) acc[i][j] += a[i] * bb[j];
        }
    }

    int gn = n0 + (tx << 3);
    float4 b0 = make_float4(0.f, 0.f, 0.f, 0.f), b1 = b0;
    if (bias) {
        b0 = *(const float4*)(bias + gn);
        b1 = *(const float4*)(bias + gn + 4);
    }
    bool do_relu = (gn < relu_limit);   // relu_limit is a multiple of 8
#pragma unroll
    for (int i = 0; i < 8; i++) {
        int gm = m0 + (ty << 3) + i;
        if (gm >= M) break;
        float4 v0 = make_float4(acc[i][0] + b0.x, acc[i][1] + b0.y,
                                acc[i][2] + b0.z, acc[i][3] + b0.w);
        float4 v1 = make_float4(acc[i][4] + b1.x, acc[i][5] + b1.y,
                                acc[i][6] + b1.z, acc[i][7] + b1.w);
        if (do_relu) {
            v0.x = fmaxf(v0.x, 0.f); v0.y = fmaxf(v0.y, 0.f);
            v0.z = fmaxf(v0.z, 0.f); v0.w = fmaxf(v0.w, 0.f);
            v1.x = fmaxf(v1.x, 0.f); v1.y = fmaxf(v1.y, 0.f);
            v1.z = fmaxf(v1.z, 0.f); v1.w = fmaxf(v1.w, 0.f);
        }
        float* crow = Cm + (size_t)gm * ldc + gn;
        *(float4*)crow       = v0;
        *(float4*)(crow + 4) = v1;
    }
}

// ---------------------------------------------------------------------------
// 6) kv_diag / K.sum over L: deterministic two-stage reduction
// ---------------------------------------------------------------------------
__global__ __launch_bounds__(256) void kvks_partial(void) {
    int c = blockIdx.x * 256 + threadIdx.x;   // 0..767
    int seg = blockIdx.y;                     // 0..15  (196 rows each)
    int b = blockIdx.z;
    const float* base = g_cat + ((size_t)b * LL + seg * 196) * NCAT;
    float skv = 0.f, sks = 0.f;
#pragma unroll 4
    for (int l = 0; l < 196; l++) {
        float kk = base[(size_t)l * NCAT + CC + c];
        float vv = base[(size_t)l * NCAT + 2 * CC + c];
        skv += kk * vv;
        sks += kk;
    }
    g_pkv[(b * 16 + seg) * CC + c] = skv;
    g_pks[(b * 16 + seg) * CC + c] = sks;
}

__global__ void kvks_reduce(void) {
    int i = blockIdx.x * 256 + threadIdx.x;   // b*CC + c
    if (i >= BB * CC) return;
    int b = i / CC, c = i % CC;
    float skv = 0.f, sks = 0.f;
#pragma unroll
    for (int s = 0; s < 16; s++) {
        skv += g_pkv[(b * 16 + s) * CC + c];
        sks += g_pks[(b * 16 + s) * CC + c];
    }
    g_kv[i] = skv;
    g_ks[i] = sks;
}

// 7) z[b,l] = 1 / (Q[b,l,:] . (ksum[b,:]+eps));  res1 = Q * kv_diag * z
__global__ __launch_bounds__(256) void zres_kernel(void) {
    int bl = blockIdx.x;
    int b = bl / LL;
    int tid = threadIdx.x;
    const float* qrow = g_cat + (size_t)bl * NCAT;   // Q at column offset 0
    float q0 = qrow[tid], q1 = qrow[tid + 256], q2 = qrow[tid + 512];
    const float* ks = g_ks + b * CC;
    float p = q0 * (ks[tid] + EPSF) + q1 * (ks[tid + 256] + EPSF) + q2 * (ks[tid + 512] + EPSF);
    float tot = block_sum256(p);
    float z = 1.0f / tot;
    const float* kv = g_kv + b * CC;
    float* out = g_res + (size_t)bl * CC;
    out[tid]       = q0 * kv[tid] * z;
    out[tid + 256] = q1 * kv[tid + 256] * z;
    out[tid + 512] = q2 * kv[tid + 512] * z;
}

// 8) Row softmax over g_mid[b, c, :]
__global__ __launch_bounds__(256) void softmax_kernel(void) {
    float* row = g_mid + (size_t)blockIdx.x * CC;
    int tid = threadIdx.x;
    float v0 = row[tid], v1 = row[tid + 256], v2 = row[tid + 512];
    float m = block_max256(fmaxf(v0, fmaxf(v1, v2)));
    __syncthreads();   // reuse of static smem between the two reductions
    float e0 = expf(v0 - m), e1 = expf(v1 - m), e2 = expf(v2 - m);
    float s = block_sum256(e0 + e1 + e2);
    float inv = 1.0f / s;
    row[tid] = e0 * inv;
    row[tid + 256] = e1 * inv;
    row[tid + 512] = e2 * inv;
}

// 9) out[b,c,l] = relu(BN(t + gamma*res2))   (tiled transpose back to NCHW)
__global__ __launch_bounds__(256) void final_kernel(const float* __restrict__ gamma,
                                                    const float* __restrict__ bw,
                                                    const float* __restrict__ bbv,
                                                    const float* __restrict__ mean,
                                                    const float* __restrict__ var,
                                                    float* __restrict__ out) {
    __shared__ float tile[32][33];
    float gm = gamma[0];
    int tx = threadIdx.x & 31, ty = threadIdx.x >> 5;
    int l0 = blockIdx.x * 32, c0 = blockIdx.y * 32, b = blockIdx.z;
#pragma unroll
    for (int i = 0; i < 4; i++) {
        int l = l0 + ty + i * 8;
        int c = c0 + tx;
        size_t ix = ((size_t)b * LL + l) * CC + c;
        float v = g_t[ix] + gm * g_res2[ix];
        v = (v - mean[c]) * rsqrtf(var[c] + BN_EPSF) * bw[c] + bbv[c];
        tile[ty + i * 8][tx] = fmaxf(v, 0.f);
    }
    __syncthreads();
#pragma unroll
    for (int i = 0; i < 4; i++) {
        int c = c0 + ty + i * 8;
        out[(size_t)(b * CC + c) * LL + l0 + tx] = tile[tx][ty + i * 8];
    }
}

// ---------------------------------------------------------------------------
// Launch
// ---------------------------------------------------------------------------
extern "C" void kernel_launch(void* const* d_in, const int* in_sizes, int n_in,
                              void* d_out, int out_size) {
    const float* x    = (const float*)d_in[0];
    const float* wq   = (const float*)d_in[1];
    const float* bq   = (const float*)d_in[2];
    const float* wk   = (const float*)d_in[3];
    const float* bk   = (const float*)d_in[4];
    const float* wv   = (const float*)d_in[5];
    const float* bv   = (const float*)d_in[6];
    const float* wq1  = (const float*)d_in[7];
    const float* bq1  = (const float*)d_in[8];
    const float* wk1  = (const float*)d_in[9];
    const float* bk1  = (const float*)d_in[10];
    const float* gam  = (const float*)d_in[11];
    const float* bn_w = (const float*)d_in[12];
    const float* bn_b = (const float*)d_in[13];
    const float* bn_m = (const float*)d_in[14];
    const float* bn_v = (const float*)d_in[15];
    const float* pw   = (const float*)d_in[16];
    const float* pb   = (const float*)d_in[17];
    float* out = (float*)d_out;

    float *p_t, *p_cat, *p_wcat, *p_bcat, *p_res, *p_mid, *p_res2;
    cudaGetSymbolAddress((void**)&p_t,    g_t);
    cudaGetSymbolAddress((void**)&p_cat,  g_cat);
    cudaGetSymbolAddress((void**)&p_wcat, g_wcat);
    cudaGetSymbolAddress((void**)&p_bcat, g_bcat);
    cudaGetSymbolAddress((void**)&p_res,  g_res);
    cudaGetSymbolAddress((void**)&p_mid,  g_mid);
    cudaGetSymbolAddress((void**)&p_res2, g_res2);

    // Positional embedding
    pe_kernel<<<(LL * 64 + 255) / 256, 256>>>();
    pos_kernel<<<LL, 256>>>(pw, pb);

    // Weight concatenation
    wcat_kernel<<<(CC * NCAT + 255) / 256, 256>>>(wq, wk, wv, wq1, wk1,
                                                  bq, bk, bv, bq1, bk1);

    // t = transpose(x) + pos
    addpos_kernel<<<dim3(LL / 32, CC / 32, BB), 256>>>(x);

    // Fused 5-way projection: [25088,768] @ [768,3840] (+bias, ReLU on Q,K cols)
    sgemm<false><<<dim3(NCAT / 128, (BB * LL) / 128, 1), 256>>>(
        p_t, CC, 0, p_wcat, NCAT, 0, p_cat, NCAT, 0,
        BB * LL, NCAT, CC, p_bcat, 2 * CC);

    // kv_diag, K.sum over L
    kvks_partial<<<dim3(CC / 256, 16, BB), 256>>>();
    kvks_reduce<<<(BB * CC + 255) / 256, 256>>>();

    // z + res1
    zres_kernel<<<BB * LL, 256>>>();

    // mid = Q1^T @ K1 per batch  (M=N=768, K=3136)
    sgemm<true><<<dim3(CC / 128, CC / 128, BB), 256>>>(
        p_cat + 3 * CC, NCAT, (size_t)LL * NCAT,
        p_cat + 4 * CC, NCAT, (size_t)LL * NCAT,
        p_mid, CC, (size_t)CC * CC,
        CC, CC, LL, nullptr, 0);

    // softmax rows of mid
    softmax_kernel<<<BB * CC, 256>>>();

    // res2 = res1 @ mid per batch  (M=3136, N=768, K=768)
    sgemm<false><<<dim3(CC / 128, (LL + 127) / 128, BB), 256>>>(
        p_res, CC, (size_t)LL * CC,
        p_mid, CC, (size_t)CC * CC,
        p_res2, CC, (size_t)LL * CC,
        LL, CC, CC, nullptr, 0);

    // BN + ReLU + transpose back to [B, C, H, W]
    final_kernel<<<dim3(LL / 32, CC / 32, BB), 256>>>(gam, bn_w, bn_b, bn_m, bn_v, out);
}

// round 3
// speedup vs baseline: 2.6206x; 2.6206x over previous
#include <cuda_runtime.h>
#include <math.h>
#include <stdint.h>

// Problem constants
#define BB   8
#define CC   768
#define HH   56
#define LL   3136           // 56*56
#define NCAT 3840           // 5*768 (Q,K,V,Q1,K1 concatenated)
#define EPSF 1e-6f
#define BN_EPSF 1e-5f

// ---------------------------------------------------------------------------
// Scratch (device globals; no allocations allowed)
// ---------------------------------------------------------------------------
static __device__ __align__(16) float g_pe[LL * 64];
static __device__ __align__(16) float g_pos[LL * CC];
static __device__ __align__(16) float g_wcat[CC * NCAT];
static __device__ __align__(16) float g_bcat[NCAT];
static __device__ __align__(16) float g_t[(size_t)BB * LL * CC];
static __device__ __align__(16) float g_cat[(size_t)BB * LL * NCAT];
static __device__ __align__(16) float g_pkv[BB * 16 * CC];
static __device__ __align__(16) float g_pks[BB * 16 * CC];
static __device__ __align__(16) float g_kv[BB * CC];
static __device__ __align__(16) float g_ks[BB * CC];
static __device__ __align__(16) float g_res[(size_t)BB * LL * CC];
static __device__ __align__(16) float g_mid[(size_t)BB * CC * CC];
static __device__ __align__(16) float g_res2[(size_t)BB * LL * CC];

// ---------------------------------------------------------------------------
// Small PTX helpers
// ---------------------------------------------------------------------------
__device__ __forceinline__ uint32_t f2tf(float x) {
    uint32_t r;
    asm("cvt.rna.tf32.f32 %0, %1;" : "=r"(r) : "f"(x));
    return r;
}

__device__ __forceinline__ void mma_tf32(float* d, const uint32_t* a, const uint32_t* b) {
    asm volatile(
        "mma.sync.aligned.m16n8k8.row.col.f32.tf32.tf32.f32 "
        "{%0,%1,%2,%3}, {%4,%5,%6,%7}, {%8,%9}, {%0,%1,%2,%3};\n"
        : "+f"(d[0]), "+f"(d[1]), "+f"(d[2]), "+f"(d[3])
        : "r"(a[0]), "r"(a[1]), "r"(a[2]), "r"(a[3]), "r"(b[0]), "r"(b[1]));
}

__device__ __forceinline__ void cp16(float* s, const float* g, bool p) {
    uint32_t sa = (uint32_t)__cvta_generic_to_shared(s);
    int sz = p ? 16 : 0;
    asm volatile("cp.async.cg.shared.global [%0], [%1], 16, %2;\n"
                 :: "r"(sa), "l"(g), "r"(sz));
}

__device__ __forceinline__ void cp_commit() {
    asm volatile("cp.async.commit_group;\n");
}
template <int N>
__device__ __forceinline__ void cp_wait() {
    asm volatile("cp.async.wait_group %0;\n" :: "n"(N));
}

// ---------------------------------------------------------------------------
// Block-wide reductions (256 threads)
// ---------------------------------------------------------------------------
__device__ __forceinline__ float block_sum256(float v) {
    __shared__ float sm[8];
    int lane = threadIdx.x & 31, w = threadIdx.x >> 5;
#pragma unroll
    for (int o = 16; o; o >>= 1) v += __shfl_xor_sync(0xffffffffu, v, o);
    if (lane == 0) sm[w] = v;
    __syncthreads();
    float t = sm[lane & 7];
#pragma unroll
    for (int o = 4; o; o >>= 1) t += __shfl_xor_sync(0xffffffffu, t, o);
    return t;
}

__device__ __forceinline__ float block_max256(float v) {
    __shared__ float sm[8];
    int lane = threadIdx.x & 31, w = threadIdx.x >> 5;
#pragma unroll
    for (int o = 16; o; o >>= 1) v = fmaxf(v, __shfl_xor_sync(0xffffffffu, v, o));
    if (lane == 0) sm[w] = v;
    __syncthreads();
    float t = sm[lane & 7];
#pragma unroll
    for (int o = 4; o; o >>= 1) t = fmaxf(t, __shfl_xor_sync(0xffffffffu, t, o));
    return t;
}

// ---------------------------------------------------------------------------
// 1) Fourier features pe[L, 64]
// ---------------------------------------------------------------------------
__global__ void pe_kernel(void) {
    int idx = blockIdx.x * 256 + threadIdx.x;
    if (idx >= LL * 64) return;
    int l = idx >> 6, k = idx & 63;
    int kk = k & 31;
    float coord = (k < 32) ? (float)(l / HH + 1) : (float)(l % HH + 1);
    float v = coord / ((float)HH + EPSF) * 6.283185307179586f;   // 2*pi
    float dt = powf(10000.0f, (float)(kk & ~1) / 32.0f);
    float p = v / dt;
    g_pe[idx] = (kk & 1) ? cosf(p) : sinf(p);
}

// 2) pos[L, C] = pe @ pos_w + pos_b   (K = 64; tiny GEMM)
__global__ __launch_bounds__(256) void pos_kernel(const float* __restrict__ pw,
                                                  const float* __restrict__ pb) {
    __shared__ float pe_s[64];
    int l = blockIdx.x;
    int tid = threadIdx.x;
    if (tid < 64) pe_s[tid] = g_pe[l * 64 + tid];
    __syncthreads();
#pragma unroll
    for (int j = 0; j < 3; j++) {
        int c = tid + j * 256;
        float acc = pb[c];
#pragma unroll 16
        for (int k = 0; k < 64; k++) acc += pe_s[k] * pw[k * CC + c];
        g_pos[(size_t)l * CC + c] = acc;
    }
}

// 3) Concatenate the 5 projection weights/biases into [768, 3840] / [3840]
__global__ void wcat_kernel(const float* __restrict__ wq, const float* __restrict__ wk,
                            const float* __restrict__ wv, const float* __restrict__ wq1,
                            const float* __restrict__ wk1,
                            const float* __restrict__ bq, const float* __restrict__ bk,
                            const float* __restrict__ bv, const float* __restrict__ bq1,
                            const float* __restrict__ bk1) {
    int idx = blockIdx.x * 256 + threadIdx.x;
    if (idx < NCAT) {
        int g = idx / CC, c = idx % CC;
        const float* bp = (g == 0) ? bq : (g == 1) ? bk : (g == 2) ? bv : (g == 3) ? bq1 : bk1;
        g_bcat[idx] = bp[c];
    }
    if (idx >= CC * NCAT) return;
    int k = idx / NCAT, n = idx % NCAT;
    int g = n / CC, c = n % CC;
    const float* wp = (g == 0) ? wq : (g == 1) ? wk : (g == 2) ? wv : (g == 3) ? wq1 : wk1;
    g_wcat[idx] = wp[k * CC + c];
}

// 4) t[b, l, c] = x[b, c, l] + pos[l, c]   (tiled transpose)
__global__ __launch_bounds__(256) void addpos_kernel(const float* __restrict__ x) {
    __shared__ float tile[32][33];
    int tx = threadIdx.x & 31, ty = threadIdx.x >> 5;       // 32 x 8
    int l0 = blockIdx.x * 32, c0 = blockIdx.y * 32, b = blockIdx.z;
#pragma unroll
    for (int i = 0; i < 4; i++) {
        int c = c0 + ty + i * 8;
        tile[ty + i * 8][tx] = x[(size_t)(b * CC + c) * LL + l0 + tx];
    }
    __syncthreads();
#pragma unroll
    for (int i = 0; i < 4; i++) {
        int l = l0 + ty + i * 8;
        int c = c0 + tx;
        g_t[((size_t)b * LL + l) * CC + c] = tile[tx][ty + i * 8] + g_pos[(size_t)l * CC + c];
    }
}

// ---------------------------------------------------------------------------
// 5) Tensor-core tf32 GEMM: C = op(A) @ B (+bias, column-conditional ReLU)
//    BM=BN=128, BK=16, 256 threads = 8 warps (4 along M x 2 along N),
//    warp tile 32x64, mma.sync.m16n8k8.tf32, fp32 accumulate.
//    cp.async double-buffered smem; cvt.rna.tf32 on the fragment path.
//    Requires N % 128 == 0 (covered by grid), K % 16 == 0. M guarded.
// ---------------------------------------------------------------------------
template <bool TRANSA, bool EPI>
__global__ __launch_bounds__(256) void gemm_tc(
    const float* __restrict__ A, int lda, size_t sA,
    const float* __restrict__ B, int ldb, size_t sB,
    float* __restrict__ C, int ldc, size_t sC,
    int M, int K, const float* __restrict__ bias, int relu_limit)
{
    // A smem: non-trans -> [m][k] stride 20 (conflict-free for A frags)
    //         trans     -> [k][m] stride 132
    constexpr int ASZ = TRANSA ? 16 * 132 : 128 * 20;
    __shared__ float As[2][ASZ];
    __shared__ float Bs[2][16 * 132];

    A += (size_t)blockIdx.z * sA;
    B += (size_t)blockIdx.z * sB;
    C += (size_t)blockIdx.z * sC;

    const int tid = threadIdx.x;
    const int m0 = blockIdx.y * 128, n0 = blockIdx.x * 128;
    const int lane = tid & 31, wid = tid >> 5;
    const int wm = wid >> 1, wn = wid & 1;
    const int tg = lane >> 2, tig = lane & 3;

    auto load_tiles = [&](int buf, int kb) {
#pragma unroll
        for (int i = 0; i < 2; i++) {
            int f = tid + i * 256;
            if (!TRANSA) {
                int row = f >> 2, col = (f & 3) << 2;
                bool p = (m0 + row) < M;
                const float* g = A + (size_t)(p ? (m0 + row) : 0) * lda + kb + col;
                cp16(&As[buf][row * 20 + col], g, p);
            } else {
                int row = f >> 5, col = (f & 31) << 2;
                const float* g = A + (size_t)(kb + row) * lda + m0 + col;
                cp16(&As[buf][row * 132 + col], g, true);
            }
        }
#pragma unroll
        for (int i = 0; i < 2; i++) {
            int f = tid + i * 256;
            int row = f >> 5, col = (f & 31) << 2;
            const float* g = B + (size_t)(kb + row) * ldb + n0 + col;
            cp16(&Bs[buf][row * 132 + col], g, true);
        }
        cp_commit();
    };

    float acc[2][8][4];
#pragma unroll
    for (int mi = 0; mi < 2; mi++)
#pragma unroll
        for (int ni = 0; ni < 8; ni++)
#pragma unroll
            for (int r = 0; r < 4; r++) acc[mi][ni][r] = 0.0f;

    const int nk = K >> 4;
    load_tiles(0, 0);

    for (int it = 0; it < nk; it++) {
        if (it + 1 < nk) {
            load_tiles((it + 1) & 1, (it + 1) << 4);
            cp_wait<1>();
        } else {
            cp_wait<0>();
        }
        __syncthreads();

        const float* as = As[it & 1];
        const float* bs = Bs[it & 1];
#pragma unroll
        for (int kk = 0; kk < 16; kk += 8) {
            uint32_t af[2][4];
#pragma unroll
            for (int mi = 0; mi < 2; mi++) {
                int mrow = wm * 32 + mi * 16 + tg;
                if (!TRANSA) {
                    const float* p = as + mrow * 20 + kk + tig;
                    af[mi][0] = f2tf(p[0]);
                    af[mi][1] = f2tf(p[8 * 20]);
                    af[mi][2] = f2tf(p[4]);
                    af[mi][3] = f2tf(p[8 * 20 + 4]);
                } else {
                    const float* p = as + (kk + tig) * 132 + mrow;
                    af[mi][0] = f2tf(p[0]);
                    af[mi][1] = f2tf(p[8]);
                    af[mi][2] = f2tf(p[4 * 132]);
                    af[mi][3] = f2tf(p[4 * 132 + 8]);
                }
            }
            uint32_t bf[8][2];
#pragma unroll
            for (int ni = 0; ni < 8; ni++) {
                const float* p = bs + (kk + tig) * 132 + wn * 64 + ni * 8 + tg;
                bf[ni][0] = f2tf(p[0]);
                bf[ni][1] = f2tf(p[4 * 132]);
            }
#pragma unroll
            for (int mi = 0; mi < 2; mi++)
#pragma unroll
                for (int ni = 0; ni < 8; ni++)
                    mma_tf32(acc[mi][ni], af[mi], bf[ni]);
        }
        __syncthreads();
    }

    // Epilogue
#pragma unroll
    for (int mi = 0; mi < 2; mi++) {
        int r0 = m0 + wm * 32 + mi * 16 + tg;
#pragma unroll
        for (int ni = 0; ni < 8; ni++) {
            int c0 = n0 + wn * 64 + ni * 8 + (tig << 1);
            float b0 = 0.f, b1 = 0.f;
            bool rl = false;
            if (EPI) {
                float2 bb = *(const float2*)(bias + c0);
                b0 = bb.x; b1 = bb.y;
                rl = c0 < relu_limit;
            }
            float v0 = acc[mi][ni][0] + b0, v1 = acc[mi][ni][1] + b1;
            float v2 = acc[mi][ni][2] + b0, v3 = acc[mi][ni][3] + b1;
            if (EPI && rl) {
                v0 = fmaxf(v0, 0.f); v1 = fmaxf(v1, 0.f);
                v2 = fmaxf(v2, 0.f); v3 = fmaxf(v3, 0.f);
            }
            if (r0 < M)
                *(float2*)(C + (size_t)r0 * ldc + c0) = make_float2(v0, v1);
            if (r0 + 8 < M)
                *(float2*)(C + (size_t)(r0 + 8) * ldc + c0) = make_float2(v2, v3);
        }
    }
}

// ---------------------------------------------------------------------------
// 6) kv_diag / K.sum over L: deterministic two-stage reduction
// ---------------------------------------------------------------------------
__global__ __launch_bounds__(256) void kvks_partial(void) {
    int c = blockIdx.x * 256 + threadIdx.x;   // 0..767
    int seg = blockIdx.y;                     // 0..15  (196 rows each)
    int b = blockIdx.z;
    const float* base = g_cat + ((size_t)b * LL + seg * 196) * NCAT;
    float skv = 0.f, sks = 0.f;
#pragma unroll 4
    for (int l = 0; l < 196; l++) {
        float kk = base[(size_t)l * NCAT + CC + c];
        float vv = base[(size_t)l * NCAT + 2 * CC + c];
        skv += kk * vv;
        sks += kk;
    }
    g_pkv[(b * 16 + seg) * CC + c] = skv;
    g_pks[(b * 16 + seg) * CC + c] = sks;
}

__global__ void kvks_reduce(void) {
    int i = blockIdx.x * 256 + threadIdx.x;   // b*CC + c
    if (i >= BB * CC) return;
    int b = i / CC, c = i % CC;
    float skv = 0.f, sks = 0.f;
#pragma unroll
    for (int s = 0; s < 16; s++) {
        skv += g_pkv[(b * 16 + s) * CC + c];
        sks += g_pks[(b * 16 + s) * CC + c];
    }
    g_kv[i] = skv;
    g_ks[i] = sks;
}

// 7) z[b,l] = 1 / (Q[b,l,:] . (ksum[b,:]+eps));  res1 = Q * kv_diag * z
__global__ __launch_bounds__(256) void zres_kernel(void) {
    int bl = blockIdx.x;
    int b = bl / LL;
    int tid = threadIdx.x;
    const float* qrow = g_cat + (size_t)bl * NCAT;   // Q at column offset 0
    float q0 = qrow[tid], q1 = qrow[tid + 256], q2 = qrow[tid + 512];
    const float* ks = g_ks + b * CC;
    float p = q0 * (ks[tid] + EPSF) + q1 * (ks[tid + 256] + EPSF) + q2 * (ks[tid + 512] + EPSF);
    float tot = block_sum256(p);
    float z = 1.0f / tot;
    const float* kv = g_kv + b * CC;
    float* out = g_res + (size_t)bl * CC;
    out[tid]       = q0 * kv[tid] * z;
    out[tid + 256] = q1 * kv[tid + 256] * z;
    out[tid + 512] = q2 * kv[tid + 512] * z;
}

// 8) Row softmax over g_mid[b, c, :]
__global__ __launch_bounds__(256) void softmax_kernel(void) {
    float* row = g_mid + (size_t)blockIdx.x * CC;
    int tid = threadIdx.x;
    float v0 = row[tid], v1 = row[tid + 256], v2 = row[tid + 512];
    float m = block_max256(fmaxf(v0, fmaxf(v1, v2)));
    __syncthreads();   // reuse of static smem between the two reductions
    float e0 = expf(v0 - m), e1 = expf(v1 - m), e2 = expf(v2 - m);
    float s = block_sum256(e0 + e1 + e2);
    float inv = 1.0f / s;
    row[tid] = e0 * inv;
    row[tid + 256] = e1 * inv;
    row[tid + 512] = e2 * inv;
}

// 9) out[b,c,l] = relu(BN(t + gamma*res2))   (tiled transpose back to NCHW)
__global__ __launch_bounds__(256) void final_kernel(const float* __restrict__ gamma,
                                                    const float* __restrict__ bw,
                                                    const float* __restrict__ bbv,
                                                    const float* __restrict__ mean,
                                                    const float* __restrict__ var,
                                                    float* __restrict__ out) {
    __shared__ float tile[32][33];
    float gm = gamma[0];
    int tx = threadIdx.x & 31, ty = threadIdx.x >> 5;
    int l0 = blockIdx.x * 32, c0 = blockIdx.y * 32, b = blockIdx.z;
#pragma unroll
    for (int i = 0; i < 4; i++) {
        int l = l0 + ty + i * 8;
        int c = c0 + tx;
        size_t ix = ((size_t)b * LL + l) * CC + c;
        float v = g_t[ix] + gm * g_res2[ix];
        v = (v - mean[c]) * rsqrtf(var[c] + BN_EPSF) * bw[c] + bbv[c];
        tile[ty + i * 8][tx] = fmaxf(v, 0.f);
    }
    __syncthreads();
#pragma unroll
    for (int i = 0; i < 4; i++) {
        int c = c0 + ty + i * 8;
        out[(size_t)(b * CC + c) * LL + l0 + tx] = tile[tx][ty + i * 8];
    }
}

// ---------------------------------------------------------------------------
// Launch
// ---------------------------------------------------------------------------
extern "C" void kernel_launch(void* const* d_in, const int* in_sizes, int n_in,
                              void* d_out, int out_size) {
    const float* x    = (const float*)d_in[0];
    const float* wq   = (const float*)d_in[1];
    const float* bq   = (const float*)d_in[2];
    const float* wk   = (const float*)d_in[3];
    const float* bk   = (const float*)d_in[4];
    const float* wv   = (const float*)d_in[5];
    const float* bv   = (const float*)d_in[6];
    const float* wq1  = (const float*)d_in[7];
    const float* bq1  = (const float*)d_in[8];
    const float* wk1  = (const float*)d_in[9];
    const float* bk1  = (const float*)d_in[10];
    const float* gam  = (const float*)d_in[11];
    const float* bn_w = (const float*)d_in[12];
    const float* bn_b = (const float*)d_in[13];
    const float* bn_m = (const float*)d_in[14];
    const float* bn_v = (const float*)d_in[15];
    const float* pw   = (const float*)d_in[16];
    const float* pb   = (const float*)d_in[17];
    float* out = (float*)d_out;

    float *p_t, *p_cat, *p_wcat, *p_bcat, *p_res, *p_mid, *p_res2;
    cudaGetSymbolAddress((void**)&p_t,    g_t);
    cudaGetSymbolAddress((void**)&p_cat,  g_cat);
    cudaGetSymbolAddress((void**)&p_wcat, g_wcat);
    cudaGetSymbolAddress((void**)&p_bcat, g_bcat);
    cudaGetSymbolAddress((void**)&p_res,  g_res);
    cudaGetSymbolAddress((void**)&p_mid,  g_mid);
    cudaGetSymbolAddress((void**)&p_res2, g_res2);

    // Positional embedding
    pe_kernel<<<(LL * 64 + 255) / 256, 256>>>();
    pos_kernel<<<LL, 256>>>(pw, pb);

    // Weight concatenation
    wcat_kernel<<<(CC * NCAT + 255) / 256, 256>>>(wq, wk, wv, wq1, wk1,
                                                  bq, bk, bv, bq1, bk1);

    // t = transpose(x) + pos
    addpos_kernel<<<dim3(LL / 32, CC / 32, BB), 256>>>(x);

    // Fused 5-way projection: [25088,768] @ [768,3840] (+bias, ReLU on Q,K cols)
    gemm_tc<false, true><<<dim3(NCAT / 128, (BB * LL) / 128, 1), 256>>>(
        p_t, CC, 0, p_wcat, NCAT, 0, p_cat, NCAT, 0,
        BB * LL, CC, p_bcat, 2 * CC);

    // kv_diag, K.sum over L
    kvks_partial<<<dim3(CC / 256, 16, BB), 256>>>();
    kvks_reduce<<<(BB * CC + 255) / 256, 256>>>();

    // z + res1
    zres_kernel<<<BB * LL, 256>>>();

    // mid = Q1^T @ K1 per batch  (M=N=768, K=3136)
    gemm_tc<true, false><<<dim3(CC / 128, CC / 128, BB), 256>>>(
        p_cat + 3 * CC, NCAT, (size_t)LL * NCAT,
        p_cat + 4 * CC, NCAT, (size_t)LL * NCAT,
        p_mid, CC, (size_t)CC * CC,
        CC, LL, nullptr, 0);

    // softmax rows of mid
    softmax_kernel<<<BB * CC, 256>>>();

    // res2 = res1 @ mid per batch  (M=3136, N=768, K=768)
    gemm_tc<false, false><<<dim3(CC / 128, (LL + 127) / 128, BB), 256>>>(
        p_res, CC, (size_t)LL * CC,
        p_mid, CC, (size_t)CC * CC,
        p_res2, CC, (size_t)LL * CC,
        LL, CC, nullptr, 0);

    // BN + ReLU + transpose back to [B, C, H, W]
    final_kernel<<<dim3(LL / 32, CC / 32, BB), 256>>>(gam, bn_w, bn_b, bn_m, bn_v, out);
}

// round 5
// speedup vs baseline: 5.1951x; 1.9824x over previous
#include <cuda_runtime.h>
#include <cuda_bf16.h>
#include <math.h>
#include <stdint.h>

// Problem constants
#define BB   8
#define CC   768
#define HH   56
#define LL   3136           // 56*56
#define NCAT 3840           // 5*768 (Q,K,V,Q1,K1)
#define CAT3 2304           // 3*768 (Q,K,V kept in fp32)
#define EPSF 1e-6f
#define BN_EPSF 1e-5f

typedef __nv_bfloat16 bf16;

// ---------------------------------------------------------------------------
// Scratch (device globals; no allocations allowed)
// ---------------------------------------------------------------------------
static __device__ __align__(16) float g_pe[LL * 64];
static __device__ __align__(16) float g_pos[LL * CC];
static __device__ __align__(16) bf16  g_wcatb[CC * NCAT];
static __device__ __align__(16) float g_bcat[NCAT];
static __device__ __align__(16) float g_t[(size_t)BB * LL * CC];
static __device__ __align__(16) bf16  g_tb[(size_t)BB * LL * CC];
static __device__ __align__(16) float g_cat[(size_t)BB * LL * CAT3];   // Q,K,V fp32
static __device__ __align__(16) bf16  g_qk1[(size_t)BB * LL * 1536];   // Q1,K1 bf16
static __device__ __align__(16) float g_pkv[BB * 16 * CC];
static __device__ __align__(16) float g_pks[BB * 16 * CC];
static __device__ __align__(16) float g_kv[BB * CC];
static __device__ __align__(16) float g_ks[BB * CC];
static __device__ __align__(16) bf16  g_resb[(size_t)BB * LL * CC];
static __device__ __align__(16) float g_mid[(size_t)BB * CC * CC];
static __device__ __align__(16) bf16  g_midb[(size_t)BB * CC * CC];
static __device__ __align__(16) float g_res2[(size_t)BB * LL * CC];

// ---------------------------------------------------------------------------
// PTX helpers
// ---------------------------------------------------------------------------
__device__ __forceinline__ void mma_bf16(float* d, const uint32_t* a, const uint32_t* b) {
    asm volatile(
        "mma.sync.aligned.m16n8k16.row.col.f32.bf16.bf16.f32 "
        "{%0,%1,%2,%3}, {%4,%5,%6,%7}, {%8,%9}, {%0,%1,%2,%3};\n"
        : "+f"(d[0]), "+f"(d[1]), "+f"(d[2]), "+f"(d[3])
        : "r"(a[0]), "r"(a[1]), "r"(a[2]), "r"(a[3]), "r"(b[0]), "r"(b[1]));
}

__device__ __forceinline__ void ldsm_x4(uint32_t* r, uint32_t addr) {
    asm volatile("ldmatrix.sync.aligned.m8n8.x4.shared.b16 {%0,%1,%2,%3}, [%4];\n"
                 : "=r"(r[0]), "=r"(r[1]), "=r"(r[2]), "=r"(r[3]) : "r"(addr));
}
__device__ __forceinline__ void ldsm_x4t(uint32_t* r, uint32_t addr) {
    asm volatile("ldmatrix.sync.aligned.m8n8.x4.trans.shared.b16 {%0,%1,%2,%3}, [%4];\n"
                 : "=r"(r[0]), "=r"(r[1]), "=r"(r[2]), "=r"(r[3]) : "r"(addr));
}

__device__ __forceinline__ void cp16(void* s, const void* g, bool p) {
    uint32_t sa = (uint32_t)__cvta_generic_to_shared(s);
    int sz = p ? 16 : 0;
    asm volatile("cp.async.cg.shared.global [%0], [%1], 16, %2;\n"
                 :: "r"(sa), "l"(g), "r"(sz));
}
__device__ __forceinline__ void cp_commit() { asm volatile("cp.async.commit_group;\n"); }
template <int N>
__device__ __forceinline__ void cp_wait() { asm volatile("cp.async.wait_group %0;\n" :: "n"(N)); }

// ---------------------------------------------------------------------------
// Block-wide reductions (256 threads)
// ---------------------------------------------------------------------------
__device__ __forceinline__ float block_sum256(float v) {
    __shared__ float sm[8];
    int lane = threadIdx.x & 31, w = threadIdx.x >> 5;
#pragma unroll
    for (int o = 16; o; o >>= 1) v += __shfl_xor_sync(0xffffffffu, v, o);
    if (lane == 0) sm[w] = v;
    __syncthreads();
    float t = sm[lane & 7];
#pragma unroll
    for (int o = 4; o; o >>= 1) t += __shfl_xor_sync(0xffffffffu, t, o);
    return t;
}

__device__ __forceinline__ float block_max256(float v) {
    __shared__ float sm[8];
    int lane = threadIdx.x & 31, w = threadIdx.x >> 5;
#pragma unroll
    for (int o = 16; o; o >>= 1) v = fmaxf(v, __shfl_xor_sync(0xffffffffu, v, o));
    if (lane == 0) sm[w] = v;
    __syncthreads();
    float t = sm[lane & 7];
#pragma unroll
    for (int o = 4; o; o >>= 1) t = fmaxf(t, __shfl_xor_sync(0xffffffffu, t, o));
    return t;
}

// ---------------------------------------------------------------------------
// 1) Fourier features pe[L, 64]
// ---------------------------------------------------------------------------
__global__ void pe_kernel(void) {
    int idx = blockIdx.x * 256 + threadIdx.x;
    if (idx >= LL * 64) return;
    int l = idx >> 6, k = idx & 63;
    int kk = k & 31;
    float coord = (k < 32) ? (float)(l / HH + 1) : (float)(l % HH + 1);
    float v = coord / ((float)HH + EPSF) * 6.283185307179586f;
    float dt = powf(10000.0f, (float)(kk & ~1) / 32.0f);
    float p = v / dt;
    g_pe[idx] = (kk & 1) ? cosf(p) : sinf(p);
}

// 2) pos[L, C] = pe @ pos_w + pos_b
__global__ __launch_bounds__(256) void pos_kernel(const float* __restrict__ pw,
                                                  const float* __restrict__ pb) {
    __shared__ float pe_s[64];
    int l = blockIdx.x;
    int tid = threadIdx.x;
    if (tid < 64) pe_s[tid] = g_pe[l * 64 + tid];
    __syncthreads();
#pragma unroll
    for (int j = 0; j < 3; j++) {
        int c = tid + j * 256;
        float acc = pb[c];
#pragma unroll 16
        for (int k = 0; k < 64; k++) acc += pe_s[k] * pw[k * CC + c];
        g_pos[(size_t)l * CC + c] = acc;
    }
}

// 3) Concatenate weights (to bf16) and biases (fp32)
__global__ void wcat_kernel(const float* __restrict__ wq, const float* __restrict__ wk,
                            const float* __restrict__ wv, const float* __restrict__ wq1,
                            const float* __restrict__ wk1,
                            const float* __restrict__ bq, const float* __restrict__ bk,
                            const float* __restrict__ bv, const float* __restrict__ bq1,
                            const float* __restrict__ bk1) {
    int idx = blockIdx.x * 256 + threadIdx.x;
    if (idx < NCAT) {
        int g = idx / CC, c = idx % CC;
        const float* bp = (g == 0) ? bq : (g == 1) ? bk : (g == 2) ? bv : (g == 3) ? bq1 : bk1;
        g_bcat[idx] = bp[c];
    }
    if (idx >= CC * NCAT) return;
    int k = idx / NCAT, n = idx % NCAT;
    int g = n / CC, c = n % CC;
    const float* wp = (g == 0) ? wq : (g == 1) ? wk : (g == 2) ? wv : (g == 3) ? wq1 : wk1;
    g_wcatb[idx] = __float2bfloat16_rn(wp[k * CC + c]);
}

// 4) t[b,l,c] = x[b,c,l] + pos[l,c]  -> fp32 (residual) + bf16 (GEMM operand)
__global__ __launch_bounds__(256) void addpos_kernel(const float* __restrict__ x) {
    __shared__ float tile[32][33];
    int tx = threadIdx.x & 31, ty = threadIdx.x >> 5;
    int l0 = blockIdx.x * 32, c0 = blockIdx.y * 32, b = blockIdx.z;
#pragma unroll
    for (int i = 0; i < 4; i++) {
        int c = c0 + ty + i * 8;
        tile[ty + i * 8][tx] = x[(size_t)(b * CC + c) * LL + l0 + tx];
    }
    __syncthreads();
#pragma unroll
    for (int i = 0; i < 4; i++) {
        int l = l0 + ty + i * 8;
        int c = c0 + tx;
        size_t ix = ((size_t)b * LL + l) * CC + c;
        float v = tile[tx][ty + i * 8] + g_pos[(size_t)l * CC + c];
        g_t[ix] = v;
        g_tb[ix] = __float2bfloat16_rn(v);
    }
}

// ---------------------------------------------------------------------------
// 5) bf16 tensor-core GEMM: C = op(A) @ B, fp32 accumulate.
//    BM=BN=128, BK=32, 256 threads (8 warps, 4x2), warp tile 32x64,
//    mma.m16n8k16.bf16, ldmatrix operand loads, cp.async double buffering.
//    MODE 0: plain fp32 store.
//    MODE 1: projection epilogue — +bias; ReLU for n<1536; n<2304 -> fp32 to
//            g_cat (ldc=2304); n>=2304 -> bf16 to g_qk1 (ld=1536).
// ---------------------------------------------------------------------------
template <bool TRANSA, int MODE>
__global__ __launch_bounds__(256) void gemm_bf(
    const bf16* __restrict__ A, int lda, size_t sA,
    const bf16* __restrict__ B, int ldb, size_t sB,
    float* __restrict__ C, int ldc, size_t sC,
    int M, int K, const float* __restrict__ bias, bf16* __restrict__ C2)
{
    constexpr int ASZ = TRANSA ? 32 * 136 : 128 * 40;
    __shared__ __align__(16) bf16 As[2][ASZ];
    __shared__ __align__(16) bf16 Bs[2][32 * 136];

    A += (size_t)blockIdx.z * sA;
    B += (size_t)blockIdx.z * sB;
    C += (size_t)blockIdx.z * sC;

    const int tid = threadIdx.x;
    const int m0 = blockIdx.y * 128, n0 = blockIdx.x * 128;
    const int lane = tid & 31, wid = tid >> 5;
    const int wm = wid >> 1, wn = wid & 1;
    const int tg = lane >> 2, tig = lane & 3;

    auto load_tiles = [&](int buf, int kb) {
#pragma unroll
        for (int i = 0; i < 2; i++) {
            int f = tid + i * 256;
            if (!TRANSA) {
                int row = f >> 2, c8 = (f & 3) << 3;          // 128 x 32
                bool p = (m0 + row) < M;
                const bf16* g = A + (size_t)(p ? (m0 + row) : 0) * lda + kb + c8;
                cp16(&As[buf][row * 40 + c8], g, p);
            } else {
                int row = f >> 4, c8 = (f & 15) << 3;         // 32 x 128
                const bf16* g = A + (size_t)(kb + row) * lda + m0 + c8;
                cp16(&As[buf][row * 136 + c8], g, true);
            }
        }
#pragma unroll
        for (int i = 0; i < 2; i++) {
            int f = tid + i * 256;
            int row = f >> 4, c8 = (f & 15) << 3;             // 32 x 128
            const bf16* g = B + (size_t)(kb + row) * ldb + n0 + c8;
            cp16(&Bs[buf][row * 136 + c8], g, true);
        }
        cp_commit();
    };

    float acc[2][8][4];
#pragma unroll
    for (int mi = 0; mi < 2; mi++)
#pragma unroll
        for (int ni = 0; ni < 8; ni++)
#pragma unroll
            for (int r = 0; r < 4; r++) acc[mi][ni][r] = 0.0f;

    // Precomputed per-lane ldmatrix offsets (element units)
    int a_off[2], b_off;
    if (!TRANSA) {
#pragma unroll
        for (int mi = 0; mi < 2; mi++)
            a_off[mi] = (wm * 32 + mi * 16 + (lane & 15)) * 40 + ((lane >> 4) << 3);
    } else {
#pragma unroll
        for (int mi = 0; mi < 2; mi++)
            a_off[mi] = (((lane >> 4) & 1) * 8 + (lane & 7)) * 136
                        + wm * 32 + mi * 16 + ((lane >> 3) & 1) * 8;
    }
    b_off = (((lane >> 3) & 1) * 8 + (lane & 7)) * 136
            + wn * 64 + ((lane >> 4) & 1) * 8;

    const int nk = K >> 5;
    load_tiles(0, 0);

    for (int it = 0; it < nk; it++) {
        if (it + 1 < nk) {
            load_tiles((it + 1) & 1, (it + 1) << 5);
            cp_wait<1>();
        } else {
            cp_wait<0>();
        }
        __syncthreads();

        uint32_t abase = (uint32_t)__cvta_generic_to_shared(As[it & 1]);
        uint32_t bbase = (uint32_t)__cvta_generic_to_shared(Bs[it & 1]);

#pragma unroll
        for (int kk = 0; kk < 32; kk += 16) {
            uint32_t af[2][4];
#pragma unroll
            for (int mi = 0; mi < 2; mi++) {
                uint32_t ad;
                if (!TRANSA) ad = abase + (uint32_t)(a_off[mi] + kk) * 2;
                else         ad = abase + (uint32_t)(a_off[mi] + kk * 136) * 2;
                if (!TRANSA) ldsm_x4(af[mi], ad);
                else         ldsm_x4t(af[mi], ad);
            }
            uint32_t bf[8][2];
#pragma unroll
            for (int ni2 = 0; ni2 < 4; ni2++) {
                uint32_t r[4];
                uint32_t bd = bbase + (uint32_t)(b_off + kk * 136 + ni2 * 16) * 2;
                ldsm_x4t(r, bd);
                bf[2 * ni2][0]     = r[0];
                bf[2 * ni2][1]     = r[1];
                bf[2 * ni2 + 1][0] = r[2];
                bf[2 * ni2 + 1][1] = r[3];
            }
#pragma unroll
            for (int mi = 0; mi < 2; mi++)
#pragma unroll
                for (int ni = 0; ni < 8; ni++)
                    mma_bf16(acc[mi][ni], af[mi], bf[ni]);
        }
        __syncthreads();
    }

    // Epilogue
#pragma unroll
    for (int mi = 0; mi < 2; mi++) {
        int r0 = m0 + wm * 32 + mi * 16 + tg;
#pragma unroll
        for (int ni = 0; ni < 8; ni++) {
            int c0 = n0 + wn * 64 + ni * 8 + (tig << 1);
            float v0 = acc[mi][ni][0], v1 = acc[mi][ni][1];
            float v2 = acc[mi][ni][2], v3 = acc[mi][ni][3];
            if (MODE == 1) {
                float2 bb = *(const float2*)(bias + c0);
                v0 += bb.x; v1 += bb.y; v2 += bb.x; v3 += bb.y;
                if (c0 < 1536) {
                    v0 = fmaxf(v0, 0.f); v1 = fmaxf(v1, 0.f);
                    v2 = fmaxf(v2, 0.f); v3 = fmaxf(v3, 0.f);
                }
                if (c0 < CAT3) {
                    if (r0 < M)
                        *(float2*)(C + (size_t)r0 * CAT3 + c0) = make_float2(v0, v1);
                    if (r0 + 8 < M)
                        *(float2*)(C + (size_t)(r0 + 8) * CAT3 + c0) = make_float2(v2, v3);
                } else {
                    int cq = c0 - CAT3;
                    if (r0 < M)
                        *(__nv_bfloat162*)(C2 + (size_t)r0 * 1536 + cq) =
                            __floats2bfloat162_rn(v0, v1);
                    if (r0 + 8 < M)
                        *(__nv_bfloat162*)(C2 + (size_t)(r0 + 8) * 1536 + cq) =
                            __floats2bfloat162_rn(v2, v3);
                }
            } else {
                if (r0 < M)
                    *(float2*)(C + (size_t)r0 * ldc + c0) = make_float2(v0, v1);
                if (r0 + 8 < M)
                    *(float2*)(C + (size_t)(r0 + 8) * ldc + c0) = make_float2(v2, v3);
            }
        }
    }
}

// ---------------------------------------------------------------------------
// 6) kv_diag / K.sum over L (reads fp32 Q,K,V in g_cat, stride CAT3)
// ---------------------------------------------------------------------------
__global__ __launch_bounds__(256) void kvks_partial(void) {
    int c = blockIdx.x * 256 + threadIdx.x;
    int seg = blockIdx.y;
    int b = blockIdx.z;
    const float* base = g_cat + ((size_t)b * LL + seg * 196) * CAT3;
    float skv = 0.f, sks = 0.f;
#pragma unroll 4
    for (int l = 0; l < 196; l++) {
        float kk = base[(size_t)l * CAT3 + CC + c];
        float vv = base[(size_t)l * CAT3 + 2 * CC + c];
        skv += kk * vv;
        sks += kk;
    }
    g_pkv[(b * 16 + seg) * CC + c] = skv;
    g_pks[(b * 16 + seg) * CC + c] = sks;
}

__global__ void kvks_reduce(void) {
    int i = blockIdx.x * 256 + threadIdx.x;
    if (i >= BB * CC) return;
    int b = i / CC, c = i % CC;
    float skv = 0.f, sks = 0.f;
#pragma unroll
    for (int s = 0; s < 16; s++) {
        skv += g_pkv[(b * 16 + s) * CC + c];
        sks += g_pks[(b * 16 + s) * CC + c];
    }
    g_kv[i] = skv;
    g_ks[i] = sks;
}

// 7) z + res1 (res written as bf16 — only consumed by gemm3)
__global__ __launch_bounds__(256) void zres_kernel(void) {
    int bl = blockIdx.x;
    int b = bl / LL;
    int tid = threadIdx.x;
    const float* qrow = g_cat + (size_t)bl * CAT3;
    float q0 = qrow[tid], q1 = qrow[tid + 256], q2 = qrow[tid + 512];
    const float* ks = g_ks + b * CC;
    float p = q0 * (ks[tid] + EPSF) + q1 * (ks[tid + 256] + EPSF) + q2 * (ks[tid + 512] + EPSF);
    float tot = block_sum256(p);
    float z = 1.0f / tot;
    const float* kv = g_kv + b * CC;
    bf16* out = g_resb + (size_t)bl * CC;
    out[tid]       = __float2bfloat16_rn(q0 * kv[tid] * z);
    out[tid + 256] = __float2bfloat16_rn(q1 * kv[tid + 256] * z);
    out[tid + 512] = __float2bfloat16_rn(q2 * kv[tid + 512] * z);
}

// 8) Row softmax over g_mid -> bf16 g_midb
__global__ __launch_bounds__(256) void softmax_kernel(void) {
    const float* row = g_mid + (size_t)blockIdx.x * CC;
    bf16* rowo = g_midb + (size_t)blockIdx.x * CC;
    int tid = threadIdx.x;
    float v0 = row[tid], v1 = row[tid + 256], v2 = row[tid + 512];
    float m = block_max256(fmaxf(v0, fmaxf(v1, v2)));
    __syncthreads();
    float e0 = expf(v0 - m), e1 = expf(v1 - m), e2 = expf(v2 - m);
    float s = block_sum256(e0 + e1 + e2);
    float inv = 1.0f / s;
    rowo[tid]       = __float2bfloat16_rn(e0 * inv);
    rowo[tid + 256] = __float2bfloat16_rn(e1 * inv);
    rowo[tid + 512] = __float2bfloat16_rn(e2 * inv);
}

// 9) out[b,c,l] = relu(BN(t + gamma*res2))
__global__ __launch_bounds__(256) void final_kernel(const float* __restrict__ gamma,
                                                    const float* __restrict__ bw,
                                                    const float* __restrict__ bbv,
                                                    const float* __restrict__ mean,
                                                    const float* __restrict__ var,
                                                    float* __restrict__ out) {
    __shared__ float tile[32][33];
    float gm = gamma[0];
    int tx = threadIdx.x & 31, ty = threadIdx.x >> 5;
    int l0 = blockIdx.x * 32, c0 = blockIdx.y * 32, b = blockIdx.z;
#pragma unroll
    for (int i = 0; i < 4; i++) {
        int l = l0 + ty + i * 8;
        int c = c0 + tx;
        size_t ix = ((size_t)b * LL + l) * CC + c;
        float v = g_t[ix] + gm * g_res2[ix];
        v = (v - mean[c]) * rsqrtf(var[c] + BN_EPSF) * bw[c] + bbv[c];
        tile[ty + i * 8][tx] = fmaxf(v, 0.f);
    }
    __syncthreads();
#pragma unroll
    for (int i = 0; i < 4; i++) {
        int c = c0 + ty + i * 8;
        out[(size_t)(b * CC + c) * LL + l0 + tx] = tile[tx][ty + i * 8];
    }
}

// ---------------------------------------------------------------------------
// Launch
// ---------------------------------------------------------------------------
extern "C" void kernel_launch(void* const* d_in, const int* in_sizes, int n_in,
                              void* d_out, int out_size) {
    const float* x    = (const float*)d_in[0];
    const float* wq   = (const float*)d_in[1];
    const float* bq   = (const float*)d_in[2];
    const float* wk   = (const float*)d_in[3];
    const float* bk   = (const float*)d_in[4];
    const float* wv   = (const float*)d_in[5];
    const float* bv   = (const float*)d_in[6];
    const float* wq1  = (const float*)d_in[7];
    const float* bq1  = (const float*)d_in[8];
    const float* wk1  = (const float*)d_in[9];
    const float* bk1  = (const float*)d_in[10];
    const float* gam  = (const float*)d_in[11];
    const float* bn_w = (const float*)d_in[12];
    const float* bn_b = (const float*)d_in[13];
    const float* bn_m = (const float*)d_in[14];
    const float* bn_v = (const float*)d_in[15];
    const float* pw   = (const float*)d_in[16];
    const float* pb   = (const float*)d_in[17];
    float* out = (float*)d_out;

    float *p_cat, *p_bcat, *p_mid, *p_res2;
    bf16 *p_tb, *p_wcatb, *p_qk1, *p_resb, *p_midb;
    cudaGetSymbolAddress((void**)&p_cat,   g_cat);
    cudaGetSymbolAddress((void**)&p_bcat,  g_bcat);
    cudaGetSymbolAddress((void**)&p_mid,   g_mid);
    cudaGetSymbolAddress((void**)&p_res2,  g_res2);
    cudaGetSymbolAddress((void**)&p_tb,    g_tb);
    cudaGetSymbolAddress((void**)&p_wcatb, g_wcatb);
    cudaGetSymbolAddress((void**)&p_qk1,   g_qk1);
    cudaGetSymbolAddress((void**)&p_resb,  g_resb);
    cudaGetSymbolAddress((void**)&p_midb,  g_midb);

    pe_kernel<<<(LL * 64 + 255) / 256, 256>>>();
    pos_kernel<<<LL, 256>>>(pw, pb);
    wcat_kernel<<<(CC * NCAT + 255) / 256, 256>>>(wq, wk, wv, wq1, wk1,
                                                  bq, bk, bv, bq1, bk1);
    addpos_kernel<<<dim3(LL / 32, CC / 32, BB), 256>>>(x);

    // Projection: [25088,768]bf16 @ [768,3840]bf16 -> Q,K,V fp32 + Q1,K1 bf16
    gemm_bf<false, 1><<<dim3(NCAT / 128, (BB * LL) / 128, 1), 256>>>(
        p_tb, CC, 0, p_wcatb, NCAT, 0, p_cat, CAT3, 0,
        BB * LL, CC, p_bcat, p_qk1);

    kvks_partial<<<dim3(CC / 256, 16, BB), 256>>>();
    kvks_reduce<<<(BB * CC + 255) / 256, 256>>>();
    zres_kernel<<<BB * LL, 256>>>();

    // mid = Q1^T @ K1 per batch (M=N=768, K=3136)
    gemm_bf<true, 0><<<dim3(CC / 128, CC / 128, BB), 256>>>(
        p_qk1, 1536, (size_t)LL * 1536,
        p_qk1 + 768, 1536, (size_t)LL * 1536,
        p_mid, CC, (size_t)CC * CC,
        CC, LL, nullptr, nullptr);

    softmax_kernel<<<BB * CC, 256>>>();

    // res2 = res1 @ mid per batch (M=3136, N=768, K=768)
    gemm_bf<false, 0><<<dim3(CC / 128, (LL + 127) / 128, BB), 256>>>(
        p_resb, CC, (size_t)LL * CC,
        p_midb, CC, (size_t)CC * CC,
        p_res2, CC, (size_t)LL * CC,
        LL, CC, nullptr, nullptr);

    final_kernel<<<dim3(LL / 32, CC / 32, BB), 256>>>(gam, bn_w, bn_b, bn_m, bn_v, out);
}